// round 1
// baseline (speedup 1.0000x reference)
#include <cuda_runtime.h>
#include <math.h>

// ---------------- problem constants ----------------
#define B     1024
#define CIN   3
#define HW    32
#define GC    16
#define E     4
#define C1    64
#define C2    128
#define NC    100
#define FCIN  8192      // 128*8*8

// output layout: [B*NC] final, [B*E] probs, [1] aux
#define OUT_PROBS_OFF (B*NC)
#define OUT_AUX_OFF   (B*NC + B*E)

// ---------------- device scratch (static: no cudaMalloc allowed) ----------------
__device__ float g_buf1[(size_t)B * C1 * 16 * 16];   // 64 MB: conv1+pool output
__device__ float g_buf2[(size_t)B * C2 * 8 * 8];     // 32 MB: conv2+pool output
__device__ float g_gpool[B * GC];
__device__ int   g_bidx[B];
__device__ float g_bw[B];
__device__ int   g_list[E * B];
__device__ int   g_count[E];

// ---------------- zero the per-expert counters ----------------
__global__ void zero_counts_kernel() {
    if (threadIdx.x < E) g_count[threadIdx.x] = 0;
}

// ---------------- gating conv (3->16, 3x3 SAME) + relu + global avg pool ----------------
__global__ void __launch_bounds__(256) gate_conv_kernel(
    const float* __restrict__ x, const float* __restrict__ gcw,
    const float* __restrict__ gcb)
{
    __shared__ float xs[CIN * 34 * 34];
    __shared__ float wg[GC * 27];
    __shared__ float gb[GC];
    __shared__ float red[256];

    int b   = blockIdx.x;
    int tid = threadIdx.x;

    for (int i = tid; i < CIN * 34 * 34; i += 256) xs[i] = 0.f;
    __syncthreads();
    const float* xb = x + (size_t)b * CIN * HW * HW;
    for (int i = tid; i < CIN * HW * HW; i += 256) {
        int ci = i >> 10, y = (i >> 5) & 31, xx = i & 31;
        xs[(ci * 34 + y + 1) * 34 + xx + 1] = xb[i];
    }
    for (int i = tid; i < GC * 27; i += 256) wg[i] = gcw[i];
    if (tid < GC) gb[tid] = gcb[tid];
    __syncthreads();

    int co = tid >> 4;     // 16 channels
    int ln = tid & 15;     // 16 threads per channel
    float w[27];
#pragma unroll
    for (int k = 0; k < 27; k++) w[k] = wg[co * 27 + k];
    float bias = gb[co];

    float s = 0.f;
    for (int p = ln; p < HW * HW; p += 16) {
        int y = p >> 5, xx = p & 31;
        float v = bias;
#pragma unroll
        for (int ci = 0; ci < CIN; ci++)
#pragma unroll
            for (int dy = 0; dy < 3; dy++)
#pragma unroll
                for (int dx = 0; dx < 3; dx++)
                    v = fmaf(xs[(ci * 34 + y + dy) * 34 + xx + dx],
                             w[ci * 9 + dy * 3 + dx], v);
        s += fmaxf(v, 0.f);
    }
    red[tid] = s;
    __syncthreads();
    if (ln == 0) {
        float t = 0.f;
#pragma unroll
        for (int j = 0; j < 16; j++) t += red[co * 16 + j];
        g_gpool[b * GC + co] = t * (1.f / (HW * HW));
    }
}

// ---------------- router: linear + softmax + argmax + per-expert gather ----------------
__global__ void router_kernel(const float* __restrict__ gfw,
                              const float* __restrict__ gfb,
                              float* __restrict__ out_probs)
{
    int b = blockIdx.x * blockDim.x + threadIdx.x;
    if (b >= B) return;
    float gp[GC];
#pragma unroll
    for (int k = 0; k < GC; k++) gp[k] = g_gpool[b * GC + k];

    float lg[E];
#pragma unroll
    for (int e = 0; e < E; e++) {
        float s = gfb[e];
#pragma unroll
        for (int k = 0; k < GC; k++) s = fmaf(gp[k], gfw[e * GC + k], s);
        lg[e] = s;
    }
    float mx = lg[0];
#pragma unroll
    for (int e = 1; e < E; e++) mx = fmaxf(mx, lg[e]);
    float ex[E], se = 0.f;
#pragma unroll
    for (int e = 0; e < E; e++) { ex[e] = expf(lg[e] - mx); se += ex[e]; }
    float inv = 1.f / se;

    float bw = -1.f; int bi = 0;
#pragma unroll
    for (int e = 0; e < E; e++) {
        float p = ex[e] * inv;
        out_probs[b * E + e] = p;
        if (p > bw) { bw = p; bi = e; }
    }
    g_bidx[b] = bi;
    g_bw[b]   = bw;
    int pos = atomicAdd(&g_count[bi], 1);
    g_list[bi * B + pos] = b;
}

// ---------------- aux loss ----------------
__global__ void aux_kernel(const float* __restrict__ probs, float* __restrict__ out)
{
    __shared__ float sm[256 * E];
    int tid = threadIdx.x;
    float s[E] = {0.f, 0.f, 0.f, 0.f};
    for (int i = tid; i < B; i += 256) {
#pragma unroll
        for (int e = 0; e < E; e++) s[e] += probs[i * E + e];
    }
#pragma unroll
    for (int e = 0; e < E; e++) sm[tid * E + e] = s[e];
    __syncthreads();
    for (int st = 128; st > 0; st >>= 1) {
        if (tid < st)
#pragma unroll
            for (int e = 0; e < E; e++) sm[tid * E + e] += sm[(tid + st) * E + e];
        __syncthreads();
    }
    if (tid == 0) {
        float a = 0.f;
#pragma unroll
        for (int e = 0; e < E; e++) {
            float m = sm[e] * (1.f / B) - 1.f / E;
            a += m * m;
        }
        out[0] = a * (1.f / E);
    }
}

// ---------------- expert conv1 (3->64) + relu + maxpool2 ----------------
__global__ void __launch_bounds__(256) conv1_kernel(
    const float* __restrict__ x, const float* __restrict__ c1w,
    const float* __restrict__ c1b)
{
    __shared__ float xs[CIN * 34 * 34];
    __shared__ float ws[C1 * 27];
    __shared__ float bs[C1];

    int b   = blockIdx.x;
    int tid = threadIdx.x;
    int e   = g_bidx[b];

    for (int i = tid; i < CIN * 34 * 34; i += 256) xs[i] = 0.f;
    __syncthreads();
    const float* xb = x + (size_t)b * CIN * HW * HW;
    for (int i = tid; i < CIN * HW * HW; i += 256) {
        int ci = i >> 10, y = (i >> 5) & 31, xx = i & 31;
        xs[(ci * 34 + y + 1) * 34 + xx + 1] = xb[i];
    }
    const float* wsrc = c1w + (size_t)e * C1 * 27;
    for (int i = tid; i < C1 * 27; i += 256) ws[i] = wsrc[i];
    if (tid < C1) bs[tid] = c1b[e * C1 + tid];
    __syncthreads();

    int co   = tid >> 2;   // 64 channels
    int quad = tid & 3;    // 4 pooled-row groups
    float w[27];
#pragma unroll
    for (int k = 0; k < 27; k++) w[k] = ws[co * 27 + k];
    float bias = bs[co];

    float* dst = g_buf1 + (size_t)b * (C1 * 256) + co * 256;

    for (int pr = 0; pr < 4; pr++) {
        int py = quad * 4 + pr;
        int Y  = 2 * py;
        for (int px = 0; px < 16; px++) {
            int X = 2 * px;
            float a00 = bias, a01 = bias, a10 = bias, a11 = bias;
#pragma unroll
            for (int ci = 0; ci < CIN; ci++) {
                float in[4][4];
#pragma unroll
                for (int iy = 0; iy < 4; iy++)
#pragma unroll
                    for (int ix = 0; ix < 4; ix++)
                        in[iy][ix] = xs[(ci * 34 + Y + iy) * 34 + X + ix];
#pragma unroll
                for (int dy = 0; dy < 3; dy++)
#pragma unroll
                    for (int dx = 0; dx < 3; dx++) {
                        float wv = w[ci * 9 + dy * 3 + dx];
                        a00 = fmaf(in[dy][dx],     wv, a00);
                        a01 = fmaf(in[dy][dx + 1], wv, a01);
                        a10 = fmaf(in[dy + 1][dx],     wv, a10);
                        a11 = fmaf(in[dy + 1][dx + 1], wv, a11);
                    }
            }
            float m = fmaxf(fmaxf(a00, a01), fmaxf(a10, a11));
            dst[py * 16 + px] = fmaxf(m, 0.f);
        }
    }
}

// ---------------- expert conv2 (64->128) + relu + maxpool2 ----------------
__global__ void __launch_bounds__(512, 1) conv2_kernel(
    const float* __restrict__ c2w, const float* __restrict__ c2b)
{
    extern __shared__ float ins[];   // [64][18][18] haloed
    int b   = blockIdx.x;
    int tid = threadIdx.x;
    int e   = g_bidx[b];

    for (int i = tid; i < C1 * 18 * 18; i += 512) ins[i] = 0.f;
    __syncthreads();
    const float* src = g_buf1 + (size_t)b * (C1 * 256);
    for (int i = tid; i < C1 * 256; i += 512) {
        int ci = i >> 8, y = (i >> 4) & 15, xx = i & 15;
        ins[(ci * 18 + y + 1) * 18 + xx + 1] = src[i];
    }
    __syncthreads();

    int co   = tid >> 2;   // 128 out channels
    int quad = tid & 3;
    int Y0   = quad * 4;   // conv rows [Y0, Y0+4)

    float acc[4][16];
    float bias = c2b[e * C2 + co];
#pragma unroll
    for (int r = 0; r < 4; r++)
#pragma unroll
        for (int xx = 0; xx < 16; xx++) acc[r][xx] = bias;

    const float* wp = c2w + (((size_t)e * C2 + co) * C1) * 9;

    for (int ci = 0; ci < C1; ci++) {
        float wr[9];
#pragma unroll
        for (int k = 0; k < 9; k++) wr[k] = wp[ci * 9 + k];
        const float* irow = &ins[(ci * 18 + Y0) * 18];
#pragma unroll
        for (int Ri = 0; Ri < 6; Ri++) {
            float rb[18];
#pragma unroll
            for (int c = 0; c < 18; c++) rb[c] = irow[Ri * 18 + c];
#pragma unroll
            for (int dy = 0; dy < 3; dy++) {
                int r = Ri - dy;
                if (r >= 0 && r < 4) {
#pragma unroll
                    for (int xx = 0; xx < 16; xx++) {
                        acc[r][xx] = fmaf(rb[xx],     wr[dy * 3],     acc[r][xx]);
                        acc[r][xx] = fmaf(rb[xx + 1], wr[dy * 3 + 1], acc[r][xx]);
                        acc[r][xx] = fmaf(rb[xx + 2], wr[dy * 3 + 2], acc[r][xx]);
                    }
                }
            }
        }
    }

    // relu + 2x2 maxpool -> pooled rows [Y0/2, Y0/2+2)
    float* dst = g_buf2 + (size_t)b * FCIN + co * 64 + (Y0 >> 1) * 8;
#pragma unroll
    for (int pr = 0; pr < 2; pr++)
#pragma unroll
        for (int pc = 0; pc < 8; pc++) {
            float m = fmaxf(fmaxf(acc[2 * pr][2 * pc], acc[2 * pr][2 * pc + 1]),
                            fmaxf(acc[2 * pr + 1][2 * pc], acc[2 * pr + 1][2 * pc + 1]));
            dst[pr * 8 + pc] = fmaxf(m, 0.f);
        }
}

// ---------------- expert FC: gathered mini-GEMM, 8 samples x 100 cols per block ----------------
#define FC_SPB 8       // samples per block
#define FC_CHUNKS (B / FC_SPB)   // 128 chunks per expert
__global__ void __launch_bounds__(256) fc_kernel(
    const float* __restrict__ fw, const float* __restrict__ fb,
    float* __restrict__ out)
{
    int e     = blockIdx.x >> 7;
    int chunk = blockIdx.x & 127;
    int n  = g_count[e];
    int s0 = chunk * FC_SPB;
    if (s0 >= n) return;
    int m = n - s0; if (m > FC_SPB) m = FC_SPB;

    __shared__ float As[FC_SPB][128];
    __shared__ int   sidx[FC_SPB];

    int tid = threadIdx.x;
    if (tid < FC_SPB) {
        int s = g_list[e * B + ((tid < m) ? (s0 + tid) : s0)];
        sidx[tid] = s;
    }
    __syncthreads();

    int r0 = sidx[0]; (void)r0;
    int sg = tid / 50;     // 0..3 (sample pair group), active if tid<200
    int cg = tid % 50;     // 0..49 (col pair group)
    bool act = (tid < 200);

    float a00 = 0.f, a01 = 0.f, a10 = 0.f, a11 = 0.f;
    const float* w0 = fw + ((size_t)e * NC + cg * 2) * FCIN;
    const float* w1 = w0 + FCIN;

    for (int k0 = 0; k0 < FCIN; k0 += 128) {
        __syncthreads();
        for (int i = tid; i < FC_SPB * 128; i += 256) {
            int r = i >> 7, kk = i & 127;
            As[r][kk] = g_buf2[(size_t)sidx[r] * FCIN + k0 + kk];
        }
        __syncthreads();
        if (act) {
#pragma unroll 4
            for (int kk = 0; kk < 128; kk++) {
                float wa = w0[k0 + kk], wb = w1[k0 + kk];
                float v0 = As[sg * 2][kk], v1 = As[sg * 2 + 1][kk];
                a00 = fmaf(v0, wa, a00);
                a01 = fmaf(v0, wb, a01);
                a10 = fmaf(v1, wa, a10);
                a11 = fmaf(v1, wb, a11);
            }
        }
    }

    if (act) {
        float accs[2][2] = {{a00, a01}, {a10, a11}};
#pragma unroll
        for (int si = 0; si < 2; si++) {
            int r = sg * 2 + si;
            if (r < m) {
                int s = sidx[r];
                float scale = g_bw[s];
#pragma unroll
                for (int cj = 0; cj < 2; cj++) {
                    int c = cg * 2 + cj;
                    out[(size_t)s * NC + c] = (accs[si][cj] + fb[e * NC + c]) * scale;
                }
            }
        }
    }
}

// ---------------- launch ----------------
extern "C" void kernel_launch(void* const* d_in, const int* in_sizes, int n_in,
                              void* d_out, int out_size)
{
    const float* x       = (const float*)d_in[0];
    const float* gate_cw = (const float*)d_in[1];
    const float* gate_cb = (const float*)d_in[2];
    const float* gate_fw = (const float*)d_in[3];
    const float* gate_fb = (const float*)d_in[4];
    const float* e_c1w   = (const float*)d_in[5];
    const float* e_c1b   = (const float*)d_in[6];
    const float* e_c2w   = (const float*)d_in[7];
    const float* e_c2b   = (const float*)d_in[8];
    const float* e_fw    = (const float*)d_in[9];
    const float* e_fb    = (const float*)d_in[10];
    float* out = (float*)d_out;

    const int conv2_smem = C1 * 18 * 18 * (int)sizeof(float);   // 82944
    cudaFuncSetAttribute(conv2_kernel,
                         cudaFuncAttributeMaxDynamicSharedMemorySize, conv2_smem);

    zero_counts_kernel<<<1, 32>>>();
    gate_conv_kernel<<<B, 256>>>(x, gate_cw, gate_cb);
    router_kernel<<<B / 256, 256>>>(gate_fw, gate_fb, out + OUT_PROBS_OFF);
    aux_kernel<<<1, 256>>>(out + OUT_PROBS_OFF, out + OUT_AUX_OFF);
    conv1_kernel<<<B, 256>>>(x, e_c1w, e_c1b);
    conv2_kernel<<<B, 512, conv2_smem>>>(e_c2w, e_c2b);
    fc_kernel<<<E * FC_CHUNKS, 256>>>(e_fw, e_fb, out);
}

// round 2
// speedup vs baseline: 1.3038x; 1.3038x over previous
#include <cuda_runtime.h>
#include <math.h>

// ---------------- problem constants ----------------
#define B     1024
#define CIN   3
#define HW    32
#define GC    16
#define E     4
#define C1    64
#define C2    128
#define NC    100
#define FCIN  8192      // 128*8*8

#define OUT_PROBS_OFF (B*NC)
#define OUT_AUX_OFF   (B*NC + B*E)

typedef unsigned long long ull;

// ---- f32x2 helpers (FFMA2) ----
__device__ __forceinline__ ull ffma2(ull a, ull b, ull c) {
    ull d;
    asm("fma.rn.f32x2 %0, %1, %2, %3;" : "=l"(d) : "l"(a), "l"(b), "l"(c));
    return d;
}
__device__ __forceinline__ ull pk(float lo, float hi) {
    ull r;
    asm("mov.b64 %0, {%1, %2};" : "=l"(r) : "f"(lo), "f"(hi));
    return r;
}
__device__ __forceinline__ void upk(ull v, float& lo, float& hi) {
    asm("mov.b64 {%0, %1}, %2;" : "=f"(lo), "=f"(hi) : "l"(v));
}

// ---------------- device scratch ----------------
__device__ float g_buf1[(size_t)B * C1 * 16 * 16];   // conv1+pool out
__device__ float g_buf2[(size_t)B * C2 * 8 * 8];     // conv2+pool out
__device__ float g_gpool[B * GC];
__device__ int   g_bidx[B];
__device__ float g_bw[B];
__device__ int   g_list[E * B];
__device__ int   g_count[E];

__global__ void zero_counts_kernel() {
    if (threadIdx.x < E) g_count[threadIdx.x] = 0;
}

// ---------------- gating conv (3->16) + relu + GAP ----------------
__global__ void __launch_bounds__(256) gate_conv_kernel(
    const float* __restrict__ x, const float* __restrict__ gcw,
    const float* __restrict__ gcb)
{
    __shared__ float xs[CIN * 34 * 34];
    __shared__ float wg[GC * 27];
    __shared__ float gb[GC];
    __shared__ float red[256];

    int b   = blockIdx.x;
    int tid = threadIdx.x;

    for (int i = tid; i < CIN * 34 * 34; i += 256) xs[i] = 0.f;
    __syncthreads();
    const float* xb = x + (size_t)b * CIN * HW * HW;
    for (int i = tid; i < CIN * HW * HW; i += 256) {
        int ci = i >> 10, y = (i >> 5) & 31, xx = i & 31;
        xs[(ci * 34 + y + 1) * 34 + xx + 1] = xb[i];
    }
    for (int i = tid; i < GC * 27; i += 256) wg[i] = gcw[i];
    if (tid < GC) gb[tid] = gcb[tid];
    __syncthreads();

    int co = tid >> 4;
    int ln = tid & 15;
    float w[27];
#pragma unroll
    for (int k = 0; k < 27; k++) w[k] = wg[co * 27 + k];
    float bias = gb[co];

    float s = 0.f;
    for (int p = ln; p < HW * HW; p += 16) {
        int y = p >> 5, xx = p & 31;
        float v = bias;
#pragma unroll
        for (int ci = 0; ci < CIN; ci++)
#pragma unroll
            for (int dy = 0; dy < 3; dy++)
#pragma unroll
                for (int dx = 0; dx < 3; dx++)
                    v = fmaf(xs[(ci * 34 + y + dy) * 34 + xx + dx],
                             w[ci * 9 + dy * 3 + dx], v);
        s += fmaxf(v, 0.f);
    }
    red[tid] = s;
    __syncthreads();
    if (ln == 0) {
        float t = 0.f;
#pragma unroll
        for (int j = 0; j < 16; j++) t += red[co * 16 + j];
        g_gpool[b * GC + co] = t * (1.f / (HW * HW));
    }
}

// ---------------- router ----------------
__global__ void router_kernel(const float* __restrict__ gfw,
                              const float* __restrict__ gfb,
                              float* __restrict__ out_probs)
{
    int b = blockIdx.x * blockDim.x + threadIdx.x;
    if (b >= B) return;
    float gp[GC];
#pragma unroll
    for (int k = 0; k < GC; k++) gp[k] = g_gpool[b * GC + k];

    float lg[E];
#pragma unroll
    for (int e = 0; e < E; e++) {
        float s = gfb[e];
#pragma unroll
        for (int k = 0; k < GC; k++) s = fmaf(gp[k], gfw[e * GC + k], s);
        lg[e] = s;
    }
    float mx = lg[0];
#pragma unroll
    for (int e = 1; e < E; e++) mx = fmaxf(mx, lg[e]);
    float ex[E], se = 0.f;
#pragma unroll
    for (int e = 0; e < E; e++) { ex[e] = expf(lg[e] - mx); se += ex[e]; }
    float inv = 1.f / se;

    float bw = -1.f; int bi = 0;
#pragma unroll
    for (int e = 0; e < E; e++) {
        float p = ex[e] * inv;
        out_probs[b * E + e] = p;
        if (p > bw) { bw = p; bi = e; }
    }
    g_bidx[b] = bi;
    g_bw[b]   = bw;
    int pos = atomicAdd(&g_count[bi], 1);
    g_list[bi * B + pos] = b;
}

// ---------------- aux loss ----------------
__global__ void aux_kernel(const float* __restrict__ probs, float* __restrict__ out)
{
    __shared__ float sm[256 * E];
    int tid = threadIdx.x;
    float s[E] = {0.f, 0.f, 0.f, 0.f};
    for (int i = tid; i < B; i += 256) {
#pragma unroll
        for (int e = 0; e < E; e++) s[e] += probs[i * E + e];
    }
#pragma unroll
    for (int e = 0; e < E; e++) sm[tid * E + e] = s[e];
    __syncthreads();
    for (int st = 128; st > 0; st >>= 1) {
        if (tid < st)
#pragma unroll
            for (int e = 0; e < E; e++) sm[tid * E + e] += sm[(tid + st) * E + e];
        __syncthreads();
    }
    if (tid == 0) {
        float a = 0.f;
#pragma unroll
        for (int e = 0; e < E; e++) {
            float m = sm[e] * (1.f / B) - 1.f / E;
            a += m * m;
        }
        out[0] = a * (1.f / E);
    }
}

// ---------------- expert conv1 (3->64) + relu + maxpool2 ----------------
__global__ void __launch_bounds__(256) conv1_kernel(
    const float* __restrict__ x, const float* __restrict__ c1w,
    const float* __restrict__ c1b)
{
    __shared__ float xs[CIN * 34 * 34];
    __shared__ float ws[C1 * 27];
    __shared__ float bs[C1];

    int b   = blockIdx.x;
    int tid = threadIdx.x;
    int e   = g_bidx[b];

    for (int i = tid; i < CIN * 34 * 34; i += 256) xs[i] = 0.f;
    __syncthreads();
    const float* xb = x + (size_t)b * CIN * HW * HW;
    for (int i = tid; i < CIN * HW * HW; i += 256) {
        int ci = i >> 10, y = (i >> 5) & 31, xx = i & 31;
        xs[(ci * 34 + y + 1) * 34 + xx + 1] = xb[i];
    }
    const float* wsrc = c1w + (size_t)e * C1 * 27;
    for (int i = tid; i < C1 * 27; i += 256) ws[i] = wsrc[i];
    if (tid < C1) bs[tid] = c1b[e * C1 + tid];
    __syncthreads();

    int co   = tid >> 2;
    int quad = tid & 3;
    float w[27];
#pragma unroll
    for (int k = 0; k < 27; k++) w[k] = ws[co * 27 + k];
    float bias = bs[co];

    float* dst = g_buf1 + (size_t)b * (C1 * 256) + co * 256;

    for (int pr = 0; pr < 4; pr++) {
        int py = quad * 4 + pr;
        int Y  = 2 * py;
        for (int px = 0; px < 16; px++) {
            int X = 2 * px;
            float a00 = bias, a01 = bias, a10 = bias, a11 = bias;
#pragma unroll
            for (int ci = 0; ci < CIN; ci++) {
                float in[4][4];
#pragma unroll
                for (int iy = 0; iy < 4; iy++)
#pragma unroll
                    for (int ix = 0; ix < 4; ix++)
                        in[iy][ix] = xs[(ci * 34 + Y + iy) * 34 + X + ix];
#pragma unroll
                for (int dy = 0; dy < 3; dy++)
#pragma unroll
                    for (int dx = 0; dx < 3; dx++) {
                        float wv = w[ci * 9 + dy * 3 + dx];
                        a00 = fmaf(in[dy][dx],     wv, a00);
                        a01 = fmaf(in[dy][dx + 1], wv, a01);
                        a10 = fmaf(in[dy + 1][dx],     wv, a10);
                        a11 = fmaf(in[dy + 1][dx + 1], wv, a11);
                    }
            }
            float m = fmaxf(fmaxf(a00, a01), fmaxf(a10, a11));
            dst[py * 16 + px] = fmaxf(m, 0.f);
        }
    }
}

// ---------------- expert conv2 (64->128) + relu + maxpool2, FFMA2 ----------------
// 2 blocks per sample (64 out channels each). 512 threads: tid>>3 = local co,
// tid&7 = 2-conv-row slice. acc2[2][8] f32x2 pairs over adjacent x.
__global__ void __launch_bounds__(512, 1) conv2_kernel(
    const float* __restrict__ c2w, const float* __restrict__ c2b)
{
    extern __shared__ float ins[];   // [64][18][18] haloed
    int bid  = blockIdx.x;
    int b    = bid >> 1;
    int half = bid & 1;
    int tid  = threadIdx.x;
    int e    = g_bidx[b];

    for (int i = tid; i < C1 * 18 * 18; i += 512) ins[i] = 0.f;
    __syncthreads();
    const float* src = g_buf1 + (size_t)b * (C1 * 256);
    for (int i = tid; i < C1 * 256; i += 512) {
        int ci = i >> 8, y = (i >> 4) & 15, xx = i & 15;
        ins[(ci * 18 + y + 1) * 18 + xx + 1] = src[i];
    }
    __syncthreads();

    int co_l  = tid >> 3;             // 0..63
    int co    = half * C1 + co_l;     // 0..127
    int slice = tid & 7;
    int Y0    = slice * 2;            // conv rows [Y0, Y0+1]

    float bias = c2b[e * C2 + co];
    ull bias2 = pk(bias, bias);
    ull acc[2][8];
#pragma unroll
    for (int r = 0; r < 2; r++)
#pragma unroll
        for (int j = 0; j < 8; j++) acc[r][j] = bias2;

    const float* wp = c2w + (((size_t)e * C2 + co) * C1) * 9;

    float wc[9];
#pragma unroll
    for (int k = 0; k < 9; k++) wc[k] = __ldg(wp + k);

    for (int ci = 0; ci < C1; ci++) {
        ull w2[9];
#pragma unroll
        for (int k = 0; k < 9; k++) w2[k] = pk(wc[k], wc[k]);

        // prefetch next channel's weights
        float wn[9];
        if (ci < C1 - 1) {
#pragma unroll
            for (int k = 0; k < 9; k++) wn[k] = __ldg(wp + (ci + 1) * 9 + k);
        }

        const float* base = ins + (ci * 18 + Y0) * 18;
#pragma unroll
        for (int Ri = 0; Ri < 4; Ri++) {
            const float2* row2 = (const float2*)(base + Ri * 18); // 8B aligned
            float2 t[9];
#pragma unroll
            for (int j = 0; j < 9; j++) t[j] = row2[j];
            ull pe[9];
#pragma unroll
            for (int j = 0; j < 9; j++) pe[j] = pk(t[j].x, t[j].y);
            ull po[8];
#pragma unroll
            for (int j = 0; j < 8; j++) po[j] = pk(t[j].y, t[j + 1].x);

#pragma unroll
            for (int dy = 0; dy < 3; dy++) {
                int lr = Ri - dy;
                if (lr >= 0 && lr < 2) {
#pragma unroll
                    for (int j = 0; j < 8; j++) {
                        acc[lr][j] = ffma2(pe[j],     w2[dy * 3 + 0], acc[lr][j]);
                        acc[lr][j] = ffma2(po[j],     w2[dy * 3 + 1], acc[lr][j]);
                        acc[lr][j] = ffma2(pe[j + 1], w2[dy * 3 + 2], acc[lr][j]);
                    }
                }
            }
        }
#pragma unroll
        for (int k = 0; k < 9; k++) wc[k] = wn[k];
    }

    // relu + 2x2 maxpool: rows (Y0,Y0+1), x pairs j -> pooled (Y0/2, j)
    float* dst = g_buf2 + (size_t)b * FCIN + co * 64 + (Y0 >> 1) * 8;
#pragma unroll
    for (int j = 0; j < 8; j++) {
        float a0, a1, b0, b1;
        upk(acc[0][j], a0, a1);
        upk(acc[1][j], b0, b1);
        float m = fmaxf(fmaxf(a0, a1), fmaxf(b0, b1));
        dst[j] = fmaxf(m, 0.f);
    }
}

// ---------------- expert FC: gathered mini-GEMM, f32x2 over k ----------------
#define FC_SPB 8
__global__ void __launch_bounds__(256) fc_kernel(
    const float* __restrict__ fw, const float* __restrict__ fb,
    float* __restrict__ out)
{
    int e     = blockIdx.x >> 7;
    int chunk = blockIdx.x & 127;
    int n  = g_count[e];
    int s0 = chunk * FC_SPB;
    if (s0 >= n) return;
    int m = n - s0; if (m > FC_SPB) m = FC_SPB;

    __shared__ float As[FC_SPB][128];
    __shared__ int   sidx[FC_SPB];

    int tid = threadIdx.x;
    if (tid < FC_SPB) {
        sidx[tid] = g_list[e * B + ((tid < m) ? (s0 + tid) : s0)];
    }
    __syncthreads();

    int sg = tid / 50;
    int cg = tid % 50;
    bool act = (tid < 200);

    ull c00 = 0, c01 = 0, c10 = 0, c11 = 0;
    const float* w0 = fw + ((size_t)e * NC + cg * 2) * FCIN;
    const float* w1 = w0 + FCIN;

    int fr  = tid >> 5;          // 0..7 row
    int fk4 = (tid & 31) * 4;    // 0..124 step 4

    for (int k0 = 0; k0 < FCIN; k0 += 128) {
        __syncthreads();
        *(float4*)&As[fr][fk4] =
            *(const float4*)&g_buf2[(size_t)sidx[fr] * FCIN + k0 + fk4];
        __syncthreads();
        if (act) {
            const float* a0 = As[sg * 2];
            const float* a1 = As[sg * 2 + 1];
#pragma unroll 16
            for (int kk = 0; kk < 128; kk += 2) {
                ull wa = *(const ull*)(w0 + k0 + kk);
                ull wb = *(const ull*)(w1 + k0 + kk);
                ull v0 = *(const ull*)(a0 + kk);
                ull v1 = *(const ull*)(a1 + kk);
                c00 = ffma2(v0, wa, c00);
                c01 = ffma2(v0, wb, c01);
                c10 = ffma2(v1, wa, c10);
                c11 = ffma2(v1, wb, c11);
            }
        }
    }

    if (act) {
        float lo, hi;
        float a[2][2];
        upk(c00, lo, hi); a[0][0] = lo + hi;
        upk(c01, lo, hi); a[0][1] = lo + hi;
        upk(c10, lo, hi); a[1][0] = lo + hi;
        upk(c11, lo, hi); a[1][1] = lo + hi;
#pragma unroll
        for (int si = 0; si < 2; si++) {
            int r = sg * 2 + si;
            if (r < m) {
                int s = sidx[r];
                float scale = g_bw[s];
#pragma unroll
                for (int cj = 0; cj < 2; cj++) {
                    int c = cg * 2 + cj;
                    out[(size_t)s * NC + c] = (a[si][cj] + fb[e * NC + c]) * scale;
                }
            }
        }
    }
}

// ---------------- launch ----------------
extern "C" void kernel_launch(void* const* d_in, const int* in_sizes, int n_in,
                              void* d_out, int out_size)
{
    const float* x       = (const float*)d_in[0];
    const float* gate_cw = (const float*)d_in[1];
    const float* gate_cb = (const float*)d_in[2];
    const float* gate_fw = (const float*)d_in[3];
    const float* gate_fb = (const float*)d_in[4];
    const float* e_c1w   = (const float*)d_in[5];
    const float* e_c1b   = (const float*)d_in[6];
    const float* e_c2w   = (const float*)d_in[7];
    const float* e_c2b   = (const float*)d_in[8];
    const float* e_fw    = (const float*)d_in[9];
    const float* e_fb    = (const float*)d_in[10];
    float* out = (float*)d_out;

    const int conv2_smem = C1 * 18 * 18 * (int)sizeof(float);   // 82944
    cudaFuncSetAttribute(conv2_kernel,
                         cudaFuncAttributeMaxDynamicSharedMemorySize, conv2_smem);

    zero_counts_kernel<<<1, 32>>>();
    gate_conv_kernel<<<B, 256>>>(x, gate_cw, gate_cb);
    router_kernel<<<B / 256, 256>>>(gate_fw, gate_fb, out + OUT_PROBS_OFF);
    aux_kernel<<<1, 256>>>(out + OUT_PROBS_OFF, out + OUT_AUX_OFF);
    conv1_kernel<<<B, 256>>>(x, e_c1w, e_c1b);
    conv2_kernel<<<2 * B, 512, conv2_smem>>>(e_c2w, e_c2b);
    fc_kernel<<<E * 128, 256>>>(e_fw, e_fb, out);
}

// round 5
// speedup vs baseline: 1.7949x; 1.3767x over previous
#include <cuda_runtime.h>
#include <cuda_fp16.h>
#include <math.h>
#include <cstdint>

// ---------------- problem constants ----------------
#define B     1024
#define CIN   3
#define HW    32
#define GC    16
#define E     4
#define C1    64
#define C2    128
#define NC    100
#define FCIN  8192      // 128*8*8
#define K2    576       // C1*9

#define OUT_PROBS_OFF (B*NC)
#define OUT_AUX_OFF   (B*NC + B*E)

typedef unsigned long long ull;

// ---- f32x2 helpers ----
__device__ __forceinline__ ull ffma2(ull a, ull b, ull c) {
    ull d;
    asm("fma.rn.f32x2 %0, %1, %2, %3;" : "=l"(d) : "l"(a), "l"(b), "l"(c));
    return d;
}
__device__ __forceinline__ void upk(ull v, float& lo, float& hi) {
    asm("mov.b64 {%0, %1}, %2;" : "=f"(lo), "=f"(hi) : "l"(v));
}

__device__ __forceinline__ uint32_t smem_u32(const void* p) {
    uint32_t a;
    asm("{ .reg .u64 t; cvta.to.shared.u64 t, %1; cvt.u32.u64 %0, t; }"
        : "=r"(a) : "l"(p));
    return a;
}
__device__ __forceinline__ void ldsm_x4(uint32_t& r0, uint32_t& r1,
                                        uint32_t& r2, uint32_t& r3, uint32_t a) {
    asm volatile("ldmatrix.sync.aligned.m8n8.x4.shared.b16 {%0,%1,%2,%3}, [%4];"
                 : "=r"(r0), "=r"(r1), "=r"(r2), "=r"(r3) : "r"(a));
}
__device__ __forceinline__ void ldsm_x2(uint32_t& r0, uint32_t& r1, uint32_t a) {
    asm volatile("ldmatrix.sync.aligned.m8n8.x2.shared.b16 {%0,%1}, [%2];"
                 : "=r"(r0), "=r"(r1) : "r"(a));
}
__device__ __forceinline__ void mma16816(float* d, const uint32_t* a,
                                         uint32_t b0, uint32_t b1) {
    asm volatile(
        "mma.sync.aligned.m16n8k16.row.col.f32.f16.f16.f32 "
        "{%0,%1,%2,%3}, {%4,%5,%6,%7}, {%8,%9}, {%0,%1,%2,%3};"
        : "+f"(d[0]), "+f"(d[1]), "+f"(d[2]), "+f"(d[3])
        : "r"(a[0]), "r"(a[1]), "r"(a[2]), "r"(a[3]), "r"(b0), "r"(b1));
}

// ---------------- device scratch ----------------
__device__ float  g_buf1[(size_t)B * C1 * 16 * 16];
__device__ float  g_buf2[(size_t)B * C2 * 8 * 8];
__device__ float  g_gpool[B * GC];
__device__ int    g_bidx[B];
__device__ float  g_bw[B];
__device__ int    g_list[E * B];
__device__ int    g_count[E];
__device__ __half g_w2h[(size_t)E * C2 * K2];
__device__ __half g_w2l[(size_t)E * C2 * K2];

__global__ void zero_counts_kernel() {
    if (threadIdx.x < E) g_count[threadIdx.x] = 0;
}

// ---------------- split conv2 weights into fp16 hi/lo ----------------
__global__ void prep_w2_kernel(const float* __restrict__ c2w) {
    int i = blockIdx.x * blockDim.x + threadIdx.x;
    if (i >= E * C2 * K2) return;
    float v = c2w[i];
    __half h = __float2half_rn(v);
    g_w2h[i] = h;
    g_w2l[i] = __float2half_rn(v - __half2float(h));
}

// ---------------- gating conv (3->16) + relu + GAP ----------------
__global__ void __launch_bounds__(256) gate_conv_kernel(
    const float* __restrict__ x, const float* __restrict__ gcw,
    const float* __restrict__ gcb)
{
    __shared__ float xs[CIN * 34 * 34];
    __shared__ float wg[GC * 27];
    __shared__ float gb[GC];
    __shared__ float red[256];

    int b   = blockIdx.x;
    int tid = threadIdx.x;

    for (int i = tid; i < CIN * 34 * 34; i += 256) xs[i] = 0.f;
    __syncthreads();
    const float* xb = x + (size_t)b * CIN * HW * HW;
    for (int i = tid; i < CIN * HW * HW; i += 256) {
        int ci = i >> 10, y = (i >> 5) & 31, xx = i & 31;
        xs[(ci * 34 + y + 1) * 34 + xx + 1] = xb[i];
    }
    for (int i = tid; i < GC * 27; i += 256) wg[i] = gcw[i];
    if (tid < GC) gb[tid] = gcb[tid];
    __syncthreads();

    int co = tid >> 4;
    int ln = tid & 15;
    float w[27];
#pragma unroll
    for (int k = 0; k < 27; k++) w[k] = wg[co * 27 + k];
    float bias = gb[co];

    float s = 0.f;
    for (int p = ln; p < HW * HW; p += 16) {
        int y = p >> 5, xx = p & 31;
        float v = bias;
#pragma unroll
        for (int ci = 0; ci < CIN; ci++)
#pragma unroll
            for (int dy = 0; dy < 3; dy++)
#pragma unroll
                for (int dx = 0; dx < 3; dx++)
                    v = fmaf(xs[(ci * 34 + y + dy) * 34 + xx + dx],
                             w[ci * 9 + dy * 3 + dx], v);
        s += fmaxf(v, 0.f);
    }
    red[tid] = s;
    __syncthreads();
    if (ln == 0) {
        float t = 0.f;
#pragma unroll
        for (int j = 0; j < 16; j++) t += red[co * 16 + j];
        g_gpool[b * GC + co] = t * (1.f / (HW * HW));
    }
}

// ---------------- router ----------------
__global__ void router_kernel(const float* __restrict__ gfw,
                              const float* __restrict__ gfb,
                              float* __restrict__ out_probs)
{
    int b = blockIdx.x * blockDim.x + threadIdx.x;
    if (b >= B) return;
    float gp[GC];
#pragma unroll
    for (int k = 0; k < GC; k++) gp[k] = g_gpool[b * GC + k];

    float lg[E];
#pragma unroll
    for (int e = 0; e < E; e++) {
        float s = gfb[e];
#pragma unroll
        for (int k = 0; k < GC; k++) s = fmaf(gp[k], gfw[e * GC + k], s);
        lg[e] = s;
    }
    float mx = lg[0];
#pragma unroll
    for (int e = 1; e < E; e++) mx = fmaxf(mx, lg[e]);
    float ex[E], se = 0.f;
#pragma unroll
    for (int e = 0; e < E; e++) { ex[e] = expf(lg[e] - mx); se += ex[e]; }
    float inv = 1.f / se;

    float bw = -1.f; int bi = 0;
#pragma unroll
    for (int e = 0; e < E; e++) {
        float p = ex[e] * inv;
        out_probs[b * E + e] = p;
        if (p > bw) { bw = p; bi = e; }
    }
    g_bidx[b] = bi;
    g_bw[b]   = bw;
    int pos = atomicAdd(&g_count[bi], 1);
    g_list[bi * B + pos] = b;
}

// ---------------- aux loss ----------------
__global__ void aux_kernel(const float* __restrict__ probs, float* __restrict__ out)
{
    __shared__ float sm[256 * E];
    int tid = threadIdx.x;
    float s[E] = {0.f, 0.f, 0.f, 0.f};
    for (int i = tid; i < B; i += 256) {
#pragma unroll
        for (int e = 0; e < E; e++) s[e] += probs[i * E + e];
    }
#pragma unroll
    for (int e = 0; e < E; e++) sm[tid * E + e] = s[e];
    __syncthreads();
    for (int st = 128; st > 0; st >>= 1) {
        if (tid < st)
#pragma unroll
            for (int e = 0; e < E; e++) sm[tid * E + e] += sm[(tid + st) * E + e];
        __syncthreads();
    }
    if (tid == 0) {
        float a = 0.f;
#pragma unroll
        for (int e = 0; e < E; e++) {
            float m = sm[e] * (1.f / B) - 1.f / E;
            a += m * m;
        }
        out[0] = a * (1.f / E);
    }
}

// ---------------- expert conv1 (3->64) + relu + maxpool2 ----------------
__global__ void __launch_bounds__(256) conv1_kernel(
    const float* __restrict__ x, const float* __restrict__ c1w,
    const float* __restrict__ c1b)
{
    __shared__ float xs[CIN * 34 * 34];
    __shared__ float ws[C1 * 27];
    __shared__ float bs[C1];

    int b   = blockIdx.x;
    int tid = threadIdx.x;
    int e   = g_bidx[b];

    for (int i = tid; i < CIN * 34 * 34; i += 256) xs[i] = 0.f;
    __syncthreads();
    const float* xb = x + (size_t)b * CIN * HW * HW;
    for (int i = tid; i < CIN * HW * HW; i += 256) {
        int ci = i >> 10, y = (i >> 5) & 31, xx = i & 31;
        xs[(ci * 34 + y + 1) * 34 + xx + 1] = xb[i];
    }
    const float* wsrc = c1w + (size_t)e * C1 * 27;
    for (int i = tid; i < C1 * 27; i += 256) ws[i] = wsrc[i];
    if (tid < C1) bs[tid] = c1b[e * C1 + tid];
    __syncthreads();

    int co   = tid >> 2;
    int quad = tid & 3;
    float w[27];
#pragma unroll
    for (int k = 0; k < 27; k++) w[k] = ws[co * 27 + k];
    float bias = bs[co];

    float* dst = g_buf1 + (size_t)b * (C1 * 256) + co * 256;

    for (int pr = 0; pr < 4; pr++) {
        int py = quad * 4 + pr;
        int Y  = 2 * py;
        for (int px = 0; px < 16; px++) {
            int X = 2 * px;
            float a00 = bias, a01 = bias, a10 = bias, a11 = bias;
#pragma unroll
            for (int ci = 0; ci < CIN; ci++) {
                float in[4][4];
#pragma unroll
                for (int iy = 0; iy < 4; iy++)
#pragma unroll
                    for (int ix = 0; ix < 4; ix++)
                        in[iy][ix] = xs[(ci * 34 + Y + iy) * 34 + X + ix];
#pragma unroll
                for (int dy = 0; dy < 3; dy++)
#pragma unroll
                    for (int dx = 0; dx < 3; dx++) {
                        float wv = w[ci * 9 + dy * 3 + dx];
                        a00 = fmaf(in[dy][dx],     wv, a00);
                        a01 = fmaf(in[dy][dx + 1], wv, a01);
                        a10 = fmaf(in[dy + 1][dx],     wv, a10);
                        a11 = fmaf(in[dy + 1][dx + 1], wv, a11);
                    }
            }
            float m = fmaxf(fmaxf(a00, a01), fmaxf(a10, a11));
            dst[py * 16 + px] = fmaxf(m, 0.f);
        }
    }
}

// ---------------- conv2 via mma.sync fp16-split implicit GEMM ----------------
// D[128co, 256px] = W[128,576] @ P[256,576]^T per sample; 3 split passes.
// smem byte offsets (A/B rows padded to 72 halves = 144 B: 16B-aligned & LDSM-conflict-free)
#define OFF_INS  0
#define OFF_AH   82944
#define OFF_AL   (OFF_AH + 128 * 72 * 2)    // +18432
#define OFF_BH   (OFF_AL + 128 * 72 * 2)    // +18432
#define OFF_BL   (OFF_BH + 256 * 72 * 2)    // +36864
#define C2_SMEM  (OFF_BL + 256 * 72 * 2)    // 193536

__global__ void __launch_bounds__(512, 1) conv2_mma_kernel(
    const float* __restrict__ c2b)
{
    extern __shared__ char smem[];
    float*  ins = (float*)(smem + OFF_INS);
    __half* Ah  = (__half*)(smem + OFF_AH);
    __half* Al  = (__half*)(smem + OFF_AL);
    __half* Bh  = (__half*)(smem + OFF_BH);
    __half* Bl  = (__half*)(smem + OFF_BL);
    uint32_t ah_b = smem_u32(Ah), al_b = smem_u32(Al);
    uint32_t bh_b = smem_u32(Bh), bl_b = smem_u32(Bl);

    int b    = blockIdx.x;
    int tid  = threadIdx.x;
    int wid  = tid >> 5;
    int lane = tid & 31;
    int e    = g_bidx[b];

    // load conv1 output tile with halo (zero padded)
    for (int i = tid; i < C1 * 18 * 18; i += 512) ins[i] = 0.f;
    __syncthreads();
    const float* src = g_buf1 + (size_t)b * (C1 * 256);
    for (int i = tid; i < C1 * 256; i += 512) {
        int ci = i >> 8, y = (i >> 4) & 15, xx = i & 15;
        ins[(ci * 18 + y + 1) * 18 + xx + 1] = src[i];
    }
    __syncthreads();

    const __half* wh = g_w2h + (size_t)e * C2 * K2;
    const __half* wl = g_w2l + (size_t)e * C2 * K2;

    // per-warp tile
    int warp_m  = wid >> 2;            // 0..3 -> co_base
    int warp_n  = wid & 3;             // 0..3 -> n_base
    int co_base = warp_m * 32;
    int n_base  = warp_n * 64;

    float acc[2][8][4];
#pragma unroll
    for (int mt = 0; mt < 2; mt++)
#pragma unroll
        for (int nt = 0; nt < 8; nt++)
#pragma unroll
            for (int j = 0; j < 4; j++) acc[mt][nt][j] = 0.f;

    // B-staging per-thread constants: n fixed
    int nB = tid & 255;
    int yB = nB >> 4, xB = nB & 15;
    int kpB0 = tid >> 8;               // 0 or 1

    // LDSM addresses (fixed part)
    uint32_t a_off = (uint32_t)((lane & 15) * 72 + (lane >> 4) * 8) * 2;
    uint32_t b_off = (uint32_t)((lane & 7) * 72 + ((lane >> 3) & 1) * 8) * 2;

    for (int chunk = 0; chunk < 9; chunk++) {
        int k0 = chunk * 64;

        // ---- stage A (weights): 128 rows x 64 halves (u32 copies) ----
#pragma unroll
        for (int it = 0; it < 8; it++) {
            int i   = tid + 512 * it;      // < 4096
            int row = i >> 5, kp = i & 31;
            uint32_t hv = *(const uint32_t*)&wh[(size_t)row * K2 + k0 + 2 * kp];
            uint32_t lv = *(const uint32_t*)&wl[(size_t)row * K2 + k0 + 2 * kp];
            *(uint32_t*)&Ah[row * 72 + 2 * kp] = hv;
            *(uint32_t*)&Al[row * 72 + 2 * kp] = lv;
        }

        // ---- stage B (im2col patches): 256 rows x 64 halves ----
#pragma unroll
        for (int it = 0; it < 16; it++) {
            int kp = kpB0 + 2 * it;        // 0..31
            int k  = k0 + 2 * kp;
            int ci0 = k / 9,   t0 = k - 9 * ci0;
            int k1v = k + 1;
            int ci1 = k1v / 9, t1 = k1v - 9 * ci1;
            float v0 = ins[(ci0 * 18 + yB + t0 / 3) * 18 + xB + t0 % 3];
            float v1 = ins[(ci1 * 18 + yB + t1 / 3) * 18 + xB + t1 % 3];
            __half h0 = __float2half_rn(v0);
            __half h1 = __float2half_rn(v1);
            __half l0 = __float2half_rn(v0 - __half2float(h0));
            __half l1 = __float2half_rn(v1 - __half2float(h1));
            *(__half2*)&Bh[nB * 72 + 2 * kp] = __halves2half2(h0, h1);
            *(__half2*)&Bl[nB * 72 + 2 * kp] = __halves2half2(l0, l1);
        }
        __syncthreads();

        // ---- MMA over 4 k-steps of 16 ----
#pragma unroll
        for (int ks = 0; ks < 4; ks++) {
            uint32_t kso = (uint32_t)(ks * 16 * 2);
            uint32_t a_h[2][4], a_l[2][4];
#pragma unroll
            for (int mt = 0; mt < 2; mt++) {
                uint32_t ra = (uint32_t)((co_base + mt * 16) * 72 * 2) + a_off + kso;
                ldsm_x4(a_h[mt][0], a_h[mt][1], a_h[mt][2], a_h[mt][3], ah_b + ra);
                ldsm_x4(a_l[mt][0], a_l[mt][1], a_l[mt][2], a_l[mt][3], al_b + ra);
            }
#pragma unroll
            for (int nt = 0; nt < 8; nt++) {
                uint32_t rb = (uint32_t)((n_base + nt * 8) * 72 * 2) + b_off + kso;
                uint32_t bh0, bh1, bl0, bl1;
                ldsm_x2(bh0, bh1, bh_b + rb);
                ldsm_x2(bl0, bl1, bl_b + rb);
#pragma unroll
                for (int mt = 0; mt < 2; mt++) {
                    mma16816(acc[mt][nt], a_h[mt], bh0, bh1);
                    mma16816(acc[mt][nt], a_h[mt], bl0, bl1);
                    mma16816(acc[mt][nt], a_l[mt], bh0, bh1);
                }
            }
        }
        __syncthreads();
    }

    // ---- epilogue: bias + relu + 2x2 maxpool ----
    int r  = lane >> 2;
    int c2 = lane & 3;
    float* dstb = g_buf2 + (size_t)b * FCIN;
#pragma unroll
    for (int mt = 0; mt < 2; mt++) {
#pragma unroll
        for (int rg = 0; rg < 2; rg++) {
            int co = co_base + mt * 16 + r + rg * 8;
            float bias = c2b[e * C2 + co];
#pragma unroll
            for (int q = 0; q < 4; q++) {
                int ntp = (q & 1) + (q >> 1) * 4;   // 0,1,4,5
                float m = fmaxf(
                    fmaxf(acc[mt][ntp][rg * 2],     acc[mt][ntp][rg * 2 + 1]),
                    fmaxf(acc[mt][ntp + 2][rg * 2], acc[mt][ntp + 2][rg * 2 + 1]));
                int py = warp_n * 2 + (ntp >> 2);
                int px = (ntp & 1) * 4 + c2;
                dstb[co * 64 + py * 8 + px] = fmaxf(m + bias, 0.f);
            }
        }
    }
}

// ---------------- expert FC: gathered mini-GEMM, f32x2 over k ----------------
#define FC_SPB 8
__global__ void __launch_bounds__(256) fc_kernel(
    const float* __restrict__ fw, const float* __restrict__ fb,
    float* __restrict__ out)
{
    int e     = blockIdx.x >> 7;
    int chunk = blockIdx.x & 127;
    int n  = g_count[e];
    int s0 = chunk * FC_SPB;
    if (s0 >= n) return;
    int m = n - s0; if (m > FC_SPB) m = FC_SPB;

    __shared__ float As[FC_SPB][128];
    __shared__ int   sidx[FC_SPB];

    int tid = threadIdx.x;
    if (tid < FC_SPB) {
        sidx[tid] = g_list[e * B + ((tid < m) ? (s0 + tid) : s0)];
    }
    __syncthreads();

    int sg = tid / 50;
    int cg = tid % 50;
    bool act = (tid < 200);

    ull c00 = 0, c01 = 0, c10 = 0, c11 = 0;
    const float* w0 = fw + ((size_t)e * NC + cg * 2) * FCIN;
    const float* w1 = w0 + FCIN;

    int fr  = tid >> 5;
    int fk4 = (tid & 31) * 4;

    for (int k0 = 0; k0 < FCIN; k0 += 128) {
        __syncthreads();
        *(float4*)&As[fr][fk4] =
            *(const float4*)&g_buf2[(size_t)sidx[fr] * FCIN + k0 + fk4];
        __syncthreads();
        if (act) {
            const float* a0 = As[sg * 2];
            const float* a1 = As[sg * 2 + 1];
#pragma unroll 16
            for (int kk = 0; kk < 128; kk += 2) {
                ull wa = *(const ull*)(w0 + k0 + kk);
                ull wb = *(const ull*)(w1 + k0 + kk);
                ull v0 = *(const ull*)(a0 + kk);
                ull v1 = *(const ull*)(a1 + kk);
                c00 = ffma2(v0, wa, c00);
                c01 = ffma2(v0, wb, c01);
                c10 = ffma2(v1, wa, c10);
                c11 = ffma2(v1, wb, c11);
            }
        }
    }

    if (act) {
        float lo, hi;
        float a[2][2];
        upk(c00, lo, hi); a[0][0] = lo + hi;
        upk(c01, lo, hi); a[0][1] = lo + hi;
        upk(c10, lo, hi); a[1][0] = lo + hi;
        upk(c11, lo, hi); a[1][1] = lo + hi;
#pragma unroll
        for (int si = 0; si < 2; si++) {
            int rr = sg * 2 + si;
            if (rr < m) {
                int s = sidx[rr];
                float scale = g_bw[s];
#pragma unroll
                for (int cj = 0; cj < 2; cj++) {
                    int c = cg * 2 + cj;
                    out[(size_t)s * NC + c] = (a[si][cj] + fb[e * NC + c]) * scale;
                }
            }
        }
    }
}

// ---------------- launch ----------------
extern "C" void kernel_launch(void* const* d_in, const int* in_sizes, int n_in,
                              void* d_out, int out_size)
{
    const float* x       = (const float*)d_in[0];
    const float* gate_cw = (const float*)d_in[1];
    const float* gate_cb = (const float*)d_in[2];
    const float* gate_fw = (const float*)d_in[3];
    const float* gate_fb = (const float*)d_in[4];
    const float* e_c1w   = (const float*)d_in[5];
    const float* e_c1b   = (const float*)d_in[6];
    const float* e_c2w   = (const float*)d_in[7];
    const float* e_c2b   = (const float*)d_in[8];
    const float* e_fw    = (const float*)d_in[9];
    const float* e_fb    = (const float*)d_in[10];
    float* out = (float*)d_out;

    cudaFuncSetAttribute(conv2_mma_kernel,
                         cudaFuncAttributeMaxDynamicSharedMemorySize, C2_SMEM);

    zero_counts_kernel<<<1, 32>>>();
    prep_w2_kernel<<<(E * C2 * K2 + 255) / 256, 256>>>(e_c2w);
    gate_conv_kernel<<<B, 256>>>(x, gate_cw, gate_cb);
    router_kernel<<<B / 256, 256>>>(gate_fw, gate_fb, out + OUT_PROBS_OFF);
    aux_kernel<<<1, 256>>>(out + OUT_PROBS_OFF, out + OUT_AUX_OFF);
    conv1_kernel<<<B, 256>>>(x, e_c1w, e_c1b);
    conv2_mma_kernel<<<B, 512, C2_SMEM>>>(e_c2b);
    fc_kernel<<<E * 128, 256>>>(e_fw, e_fb, out);
}

// round 6
// speedup vs baseline: 1.9512x; 1.0871x over previous
#include <cuda_runtime.h>
#include <cuda_fp16.h>
#include <math.h>
#include <cstdint>

// ---------------- problem constants ----------------
#define B     1024
#define CIN   3
#define HW    32
#define GC    16
#define E     4
#define C1    64
#define C2    128
#define NC    100
#define FCIN  8192      // 128*8*8

#define NPIX  324       // 18*18 haloed conv1 output grid
#define ROWP  72        // padded row length (halves); 144B stride

#define OUT_PROBS_OFF (B*NC)
#define OUT_AUX_OFF   (B*NC + B*E)

typedef unsigned long long ull;

// ---- f32x2 helpers ----
__device__ __forceinline__ ull ffma2(ull a, ull b, ull c) {
    ull d;
    asm("fma.rn.f32x2 %0, %1, %2, %3;" : "=l"(d) : "l"(a), "l"(b), "l"(c));
    return d;
}
__device__ __forceinline__ void upk(ull v, float& lo, float& hi) {
    asm("mov.b64 {%0, %1}, %2;" : "=f"(lo), "=f"(hi) : "l"(v));
}

__device__ __forceinline__ uint32_t smem_u32(const void* p) {
    uint32_t a;
    asm("{ .reg .u64 t; cvta.to.shared.u64 t, %1; cvt.u32.u64 %0, t; }"
        : "=r"(a) : "l"(p));
    return a;
}
__device__ __forceinline__ void ldsm_x4(uint32_t& r0, uint32_t& r1,
                                        uint32_t& r2, uint32_t& r3, uint32_t a) {
    asm volatile("ldmatrix.sync.aligned.m8n8.x4.shared.b16 {%0,%1,%2,%3}, [%4];"
                 : "=r"(r0), "=r"(r1), "=r"(r2), "=r"(r3) : "r"(a));
}
__device__ __forceinline__ void ldsm_x2(uint32_t& r0, uint32_t& r1, uint32_t a) {
    asm volatile("ldmatrix.sync.aligned.m8n8.x2.shared.b16 {%0,%1}, [%2];"
                 : "=r"(r0), "=r"(r1) : "r"(a));
}
__device__ __forceinline__ void mma16816(float* d, const uint32_t* a,
                                         uint32_t b0, uint32_t b1) {
    asm volatile(
        "mma.sync.aligned.m16n8k16.row.col.f32.f16.f16.f32 "
        "{%0,%1,%2,%3}, {%4,%5,%6,%7}, {%8,%9}, {%0,%1,%2,%3};"
        : "+f"(d[0]), "+f"(d[1]), "+f"(d[2]), "+f"(d[3])
        : "r"(a[0]), "r"(a[1]), "r"(a[2]), "r"(a[3]), "r"(b0), "r"(b1));
}

// ---------------- device scratch (zero-initialized; halo/pad cells stay 0) ----
__device__ __half g_b1h[(size_t)B * NPIX * ROWP];   // conv1 out hi, [b][pix][ci]
__device__ __half g_b1l[(size_t)B * NPIX * ROWP];   // conv1 out lo
__device__ float  g_buf2[(size_t)B * C2 * 8 * 8];   // conv2+pool out
__device__ float  g_gpool[B * GC];
__device__ int    g_bidx[B];
__device__ float  g_bw[B];
__device__ int    g_list[E * B];
__device__ int    g_count[E];
__device__ __half g_w2h[(size_t)E * 9 * C2 * C1];   // [e][tap][co][ci]
__device__ __half g_w2l[(size_t)E * 9 * C2 * C1];

__global__ void zero_counts_kernel() {
    if (threadIdx.x < E) g_count[threadIdx.x] = 0;
}

// ---------------- split + transpose conv2 weights: [e][tap][co][ci] ----------
__global__ void prep_w2_kernel(const float* __restrict__ c2w) {
    int i = blockIdx.x * blockDim.x + threadIdx.x;
    if (i >= E * 9 * C2 * C1) return;
    int ci   = i & 63;
    int co   = (i >> 6) & 127;
    int rest = i >> 13;            // e*9 + tap
    int tap  = rest % 9;
    int e    = rest / 9;
    float v = c2w[(((size_t)(e * C2 + co)) * C1 + ci) * 9 + tap];
    __half h = __float2half_rn(v);
    g_w2h[i] = h;
    g_w2l[i] = __float2half_rn(v - __half2float(h));
}

// ---------------- gating conv (3->16) + relu + GAP ----------------
__global__ void __launch_bounds__(256) gate_conv_kernel(
    const float* __restrict__ x, const float* __restrict__ gcw,
    const float* __restrict__ gcb)
{
    __shared__ float xs[CIN * 34 * 34];
    __shared__ float wg[GC * 27];
    __shared__ float gb[GC];
    __shared__ float red[256];

    int b   = blockIdx.x;
    int tid = threadIdx.x;

    for (int i = tid; i < CIN * 34 * 34; i += 256) xs[i] = 0.f;
    __syncthreads();
    const float* xb = x + (size_t)b * CIN * HW * HW;
    for (int i = tid; i < CIN * HW * HW; i += 256) {
        int ci = i >> 10, y = (i >> 5) & 31, xx = i & 31;
        xs[(ci * 34 + y + 1) * 34 + xx + 1] = xb[i];
    }
    for (int i = tid; i < GC * 27; i += 256) wg[i] = gcw[i];
    if (tid < GC) gb[tid] = gcb[tid];
    __syncthreads();

    int co = tid >> 4;
    int ln = tid & 15;
    float w[27];
#pragma unroll
    for (int k = 0; k < 27; k++) w[k] = wg[co * 27 + k];
    float bias = gb[co];

    float s = 0.f;
    for (int p = ln; p < HW * HW; p += 16) {
        int y = p >> 5, xx = p & 31;
        float v = bias;
#pragma unroll
        for (int ci = 0; ci < CIN; ci++)
#pragma unroll
            for (int dy = 0; dy < 3; dy++)
#pragma unroll
                for (int dx = 0; dx < 3; dx++)
                    v = fmaf(xs[(ci * 34 + y + dy) * 34 + xx + dx],
                             w[ci * 9 + dy * 3 + dx], v);
        s += fmaxf(v, 0.f);
    }
    red[tid] = s;
    __syncthreads();
    if (ln == 0) {
        float t = 0.f;
#pragma unroll
        for (int j = 0; j < 16; j++) t += red[co * 16 + j];
        g_gpool[b * GC + co] = t * (1.f / (HW * HW));
    }
}

// ---------------- router ----------------
__global__ void router_kernel(const float* __restrict__ gfw,
                              const float* __restrict__ gfb,
                              float* __restrict__ out_probs)
{
    int b = blockIdx.x * blockDim.x + threadIdx.x;
    if (b >= B) return;
    float gp[GC];
#pragma unroll
    for (int k = 0; k < GC; k++) gp[k] = g_gpool[b * GC + k];

    float lg[E];
#pragma unroll
    for (int e = 0; e < E; e++) {
        float s = gfb[e];
#pragma unroll
        for (int k = 0; k < GC; k++) s = fmaf(gp[k], gfw[e * GC + k], s);
        lg[e] = s;
    }
    float mx = lg[0];
#pragma unroll
    for (int e = 1; e < E; e++) mx = fmaxf(mx, lg[e]);
    float ex[E], se = 0.f;
#pragma unroll
    for (int e = 0; e < E; e++) { ex[e] = expf(lg[e] - mx); se += ex[e]; }
    float inv = 1.f / se;

    float bw = -1.f; int bi = 0;
#pragma unroll
    for (int e = 0; e < E; e++) {
        float p = ex[e] * inv;
        out_probs[b * E + e] = p;
        if (p > bw) { bw = p; bi = e; }
    }
    g_bidx[b] = bi;
    g_bw[b]   = bw;
    int pos = atomicAdd(&g_count[bi], 1);
    g_list[bi * B + pos] = b;
}

// ---------------- aux loss ----------------
__global__ void aux_kernel(const float* __restrict__ probs, float* __restrict__ out)
{
    __shared__ float sm[256 * E];
    int tid = threadIdx.x;
    float s[E] = {0.f, 0.f, 0.f, 0.f};
    for (int i = tid; i < B; i += 256) {
#pragma unroll
        for (int e = 0; e < E; e++) s[e] += probs[i * E + e];
    }
#pragma unroll
    for (int e = 0; e < E; e++) sm[tid * E + e] = s[e];
    __syncthreads();
    for (int st = 128; st > 0; st >>= 1) {
        if (tid < st)
#pragma unroll
            for (int e = 0; e < E; e++) sm[tid * E + e] += sm[(tid + st) * E + e];
        __syncthreads();
    }
    if (tid == 0) {
        float a = 0.f;
#pragma unroll
        for (int e = 0; e < E; e++) {
            float m = sm[e] * (1.f / B) - 1.f / E;
            a += m * m;
        }
        out[0] = a * (1.f / E);
    }
}

// ---------------- expert conv1 (3->64) + relu + maxpool2 ----------------
// writes hi/lo fp16 in transposed halo layout [b][pix(18x18)][ci], rows padded to 72
__global__ void __launch_bounds__(256) conv1_kernel(
    const float* __restrict__ x, const float* __restrict__ c1w,
    const float* __restrict__ c1b)
{
    __shared__ float xs[CIN * 34 * 34];
    __shared__ float ws[C1 * 27];
    __shared__ float bs[C1];

    int b   = blockIdx.x;
    int tid = threadIdx.x;
    int e   = g_bidx[b];

    for (int i = tid; i < CIN * 34 * 34; i += 256) xs[i] = 0.f;
    __syncthreads();
    const float* xb = x + (size_t)b * CIN * HW * HW;
    for (int i = tid; i < CIN * HW * HW; i += 256) {
        int ci = i >> 10, y = (i >> 5) & 31, xx = i & 31;
        xs[(ci * 34 + y + 1) * 34 + xx + 1] = xb[i];
    }
    const float* wsrc = c1w + (size_t)e * C1 * 27;
    for (int i = tid; i < C1 * 27; i += 256) ws[i] = wsrc[i];
    if (tid < C1) bs[tid] = c1b[e * C1 + tid];
    __syncthreads();

    int co   = tid >> 2;
    int quad = tid & 3;
    float w[27];
#pragma unroll
    for (int k = 0; k < 27; k++) w[k] = ws[co * 27 + k];
    float bias = bs[co];

    __half* dsth = g_b1h + (size_t)b * NPIX * ROWP;
    __half* dstl = g_b1l + (size_t)b * NPIX * ROWP;

    for (int pr = 0; pr < 4; pr++) {
        int py = quad * 4 + pr;
        int Y  = 2 * py;
        for (int px = 0; px < 16; px++) {
            int X = 2 * px;
            float a00 = bias, a01 = bias, a10 = bias, a11 = bias;
#pragma unroll
            for (int ci = 0; ci < CIN; ci++) {
                float in[4][4];
#pragma unroll
                for (int iy = 0; iy < 4; iy++)
#pragma unroll
                    for (int ix = 0; ix < 4; ix++)
                        in[iy][ix] = xs[(ci * 34 + Y + iy) * 34 + X + ix];
#pragma unroll
                for (int dy = 0; dy < 3; dy++)
#pragma unroll
                    for (int dx = 0; dx < 3; dx++) {
                        float wv = w[ci * 9 + dy * 3 + dx];
                        a00 = fmaf(in[dy][dx],     wv, a00);
                        a01 = fmaf(in[dy][dx + 1], wv, a01);
                        a10 = fmaf(in[dy + 1][dx],     wv, a10);
                        a11 = fmaf(in[dy + 1][dx + 1], wv, a11);
                    }
            }
            float m = fmaxf(fmaxf(a00, a01), fmaxf(a10, a11));
            float v = fmaxf(m, 0.f);
            __half h = __float2half_rn(v);
            int pix = (py + 1) * 18 + (px + 1);
            dsth[pix * ROWP + co] = h;
            dstl[pix * ROWP + co] = __float2half_rn(v - __half2float(h));
        }
    }
}

// ---------------- conv2: tap-decomposed HMMA GEMM ----------------
// D[128co,256px] = sum_{tap} W_tap[128,64] @ In_shift(tap)[256px,64]^T; fp16 split x3.
#define OFF_BH2   0
#define OFF_BL2   (NPIX * ROWP * 2)                 // 46656
#define OFF_A2    (2 * NPIX * ROWP * 2)             // 93312
#define A_BUF_SZ  (2 * C2 * ROWP * 2)               // hi+lo per buffer: 36864
#define C2_SMEM   (OFF_A2 + 2 * A_BUF_SZ)           // 167040

__global__ void __launch_bounds__(512, 1) conv2_mma_kernel(
    const float* __restrict__ c2b)
{
    extern __shared__ char smem[];
    uint32_t sb = smem_u32(smem);

    int b    = blockIdx.x;
    int tid  = threadIdx.x;
    int wid  = tid >> 5;
    int lane = tid & 31;
    int e    = g_bidx[b];

    // ---- load input hi/lo [324][72] (contiguous copy; halo already zero) ----
    {
        const uint32_t* srch = (const uint32_t*)(g_b1h + (size_t)b * NPIX * ROWP);
        const uint32_t* srcl = (const uint32_t*)(g_b1l + (size_t)b * NPIX * ROWP);
        uint32_t* dh = (uint32_t*)(smem + OFF_BH2);
        uint32_t* dl = (uint32_t*)(smem + OFF_BL2);
        for (int i = tid; i < NPIX * ROWP / 2; i += 512) {
            dh[i] = srch[i];
            dl[i] = srcl[i];
        }
    }

    const __half* wsrch = g_w2h + (size_t)e * 9 * C2 * C1;
    const __half* wsrcl = g_w2l + (size_t)e * 9 * C2 * C1;

    // stage weights for one tap into buffer buf (rows padded to 72)
    int arow = tid >> 2, aseg = tid & 3;
    auto stageA = [&](int tap, int buf) {
        const uint4* sh = (const uint4*)&wsrch[(size_t)(tap * C2 + arow) * C1 + aseg * 16];
        const uint4* sl = (const uint4*)&wsrcl[(size_t)(tap * C2 + arow) * C1 + aseg * 16];
        uint4* dh = (uint4*)(smem + OFF_A2 + buf * A_BUF_SZ + (arow * ROWP + aseg * 16) * 2);
        uint4* dl = (uint4*)(smem + OFF_A2 + buf * A_BUF_SZ + C2 * ROWP * 2
                             + (arow * ROWP + aseg * 16) * 2);
        dh[0] = sh[0]; dh[1] = sh[1];
        dl[0] = sl[0]; dl[1] = sl[1];
    };

    stageA(0, 0);
    __syncthreads();

    int warp_m  = wid >> 2;
    int warp_n  = wid & 3;
    int co_base = warp_m * 32;

    float acc[2][8][4];
#pragma unroll
    for (int mt = 0; mt < 2; mt++)
#pragma unroll
        for (int nt = 0; nt < 8; nt++)
#pragma unroll
            for (int j = 0; j < 4; j++) acc[mt][nt][j] = 0.f;

    uint32_t a_off = (uint32_t)((lane & 15) * ROWP + (lane >> 4) * 8) * 2;
    int br = lane & 7;                    // B row within tile
    int bk = ((lane >> 3) & 1) * 16;      // B k-half offset (bytes)

    for (int tap = 0; tap < 9; tap++) {
        if (tap + 1 < 9) stageA(tap + 1, (tap + 1) & 1);
        int dy = tap / 3, dx = tap % 3;
        uint32_t abase_h = sb + OFF_A2 + (tap & 1) * A_BUF_SZ;
        uint32_t abase_l = abase_h + C2 * ROWP * 2;

#pragma unroll
        for (int ks = 0; ks < 4; ks++) {
            uint32_t kso = (uint32_t)(ks * 32);
            uint32_t a_h[2][4], a_l[2][4];
#pragma unroll
            for (int mt = 0; mt < 2; mt++) {
                uint32_t ra = (uint32_t)((co_base + mt * 16) * ROWP * 2) + a_off + kso;
                ldsm_x4(a_h[mt][0], a_h[mt][1], a_h[mt][2], a_h[mt][3], abase_h + ra);
                ldsm_x4(a_l[mt][0], a_l[mt][1], a_l[mt][2], a_l[mt][3], abase_l + ra);
            }
#pragma unroll
            for (int nt = 0; nt < 8; nt++) {
                int y  = warp_n * 4 + (nt >> 1);
                int x0 = (nt & 1) * 8;
                uint32_t rrow = (uint32_t)((y + dy) * 18 + x0 + dx + br);
                uint32_t rb   = rrow * (ROWP * 2) + bk + kso;
                uint32_t bh0, bh1, bl0, bl1;
                ldsm_x2(bh0, bh1, sb + OFF_BH2 + rb);
                ldsm_x2(bl0, bl1, sb + OFF_BL2 + rb);
#pragma unroll
                for (int mt = 0; mt < 2; mt++) {
                    mma16816(acc[mt][nt], a_h[mt], bh0, bh1);
                    mma16816(acc[mt][nt], a_h[mt], bl0, bl1);
                    mma16816(acc[mt][nt], a_l[mt], bh0, bh1);
                }
            }
        }
        __syncthreads();
    }

    // ---- epilogue: bias + relu + 2x2 maxpool ----
    int r  = lane >> 2;
    int c2 = lane & 3;
    float* dstb = g_buf2 + (size_t)b * FCIN;
#pragma unroll
    for (int mt = 0; mt < 2; mt++) {
#pragma unroll
        for (int rg = 0; rg < 2; rg++) {
            int co = co_base + mt * 16 + r + rg * 8;
            float bias = c2b[e * C2 + co];
#pragma unroll
            for (int q = 0; q < 4; q++) {
                int ntp = (q & 1) + (q >> 1) * 4;   // 0,1,4,5
                float m = fmaxf(
                    fmaxf(acc[mt][ntp][rg * 2],     acc[mt][ntp][rg * 2 + 1]),
                    fmaxf(acc[mt][ntp + 2][rg * 2], acc[mt][ntp + 2][rg * 2 + 1]));
                int py = warp_n * 2 + (ntp >> 2);
                int px = (ntp & 1) * 4 + c2;
                dstb[co * 64 + py * 8 + px] = fmaxf(m + bias, 0.f);
            }
        }
    }
}

// ---------------- expert FC: gathered mini-GEMM, f32x2 over k ----------------
#define FC_SPB 8
__global__ void __launch_bounds__(256) fc_kernel(
    const float* __restrict__ fw, const float* __restrict__ fb,
    float* __restrict__ out)
{
    int e     = blockIdx.x >> 7;
    int chunk = blockIdx.x & 127;
    int n  = g_count[e];
    int s0 = chunk * FC_SPB;
    if (s0 >= n) return;
    int m = n - s0; if (m > FC_SPB) m = FC_SPB;

    __shared__ float As[FC_SPB][128];
    __shared__ int   sidx[FC_SPB];

    int tid = threadIdx.x;
    if (tid < FC_SPB) {
        sidx[tid] = g_list[e * B + ((tid < m) ? (s0 + tid) : s0)];
    }
    __syncthreads();

    int sg = tid / 50;
    int cg = tid % 50;
    bool act = (tid < 200);

    ull c00 = 0, c01 = 0, c10 = 0, c11 = 0;
    const float* w0 = fw + ((size_t)e * NC + cg * 2) * FCIN;
    const float* w1 = w0 + FCIN;

    int fr  = tid >> 5;
    int fk4 = (tid & 31) * 4;

    for (int k0 = 0; k0 < FCIN; k0 += 128) {
        __syncthreads();
        *(float4*)&As[fr][fk4] =
            *(const float4*)&g_buf2[(size_t)sidx[fr] * FCIN + k0 + fk4];
        __syncthreads();
        if (act) {
            const float* a0 = As[sg * 2];
            const float* a1 = As[sg * 2 + 1];
#pragma unroll 16
            for (int kk = 0; kk < 128; kk += 2) {
                ull wa = *(const ull*)(w0 + k0 + kk);
                ull wb = *(const ull*)(w1 + k0 + kk);
                ull v0 = *(const ull*)(a0 + kk);
                ull v1 = *(const ull*)(a1 + kk);
                c00 = ffma2(v0, wa, c00);
                c01 = ffma2(v0, wb, c01);
                c10 = ffma2(v1, wa, c10);
                c11 = ffma2(v1, wb, c11);
            }
        }
    }

    if (act) {
        float lo, hi;
        float a[2][2];
        upk(c00, lo, hi); a[0][0] = lo + hi;
        upk(c01, lo, hi); a[0][1] = lo + hi;
        upk(c10, lo, hi); a[1][0] = lo + hi;
        upk(c11, lo, hi); a[1][1] = lo + hi;
#pragma unroll
        for (int si = 0; si < 2; si++) {
            int rr = sg * 2 + si;
            if (rr < m) {
                int s = sidx[rr];
                float scale = g_bw[s];
#pragma unroll
                for (int cj = 0; cj < 2; cj++) {
                    int c = cg * 2 + cj;
                    out[(size_t)s * NC + c] = (a[si][cj] + fb[e * NC + c]) * scale;
                }
            }
        }
    }
}

// ---------------- launch ----------------
extern "C" void kernel_launch(void* const* d_in, const int* in_sizes, int n_in,
                              void* d_out, int out_size)
{
    const float* x       = (const float*)d_in[0];
    const float* gate_cw = (const float*)d_in[1];
    const float* gate_cb = (const float*)d_in[2];
    const float* gate_fw = (const float*)d_in[3];
    const float* gate_fb = (const float*)d_in[4];
    const float* e_c1w   = (const float*)d_in[5];
    const float* e_c1b   = (const float*)d_in[6];
    const float* e_c2w   = (const float*)d_in[7];
    const float* e_c2b   = (const float*)d_in[8];
    const float* e_fw    = (const float*)d_in[9];
    const float* e_fb    = (const float*)d_in[10];
    float* out = (float*)d_out;

    cudaFuncSetAttribute(conv2_mma_kernel,
                         cudaFuncAttributeMaxDynamicSharedMemorySize, C2_SMEM);

    zero_counts_kernel<<<1, 32>>>();
    prep_w2_kernel<<<(E * 9 * C2 * C1 + 255) / 256, 256>>>(e_c2w);
    gate_conv_kernel<<<B, 256>>>(x, gate_cw, gate_cb);
    router_kernel<<<B / 256, 256>>>(gate_fw, gate_fb, out + OUT_PROBS_OFF);
    aux_kernel<<<1, 256>>>(out + OUT_PROBS_OFF, out + OUT_AUX_OFF);
    conv1_kernel<<<B, 256>>>(x, e_c1w, e_c1b);
    conv2_mma_kernel<<<B, 512, C2_SMEM>>>(e_c2b);
    fc_kernel<<<E * 128, 256>>>(e_fw, e_fb, out);
}